// round 17
// baseline (speedup 1.0000x reference)
#include <cuda_runtime.h>
#include <cuda_fp16.h>
#include <math.h>

#define HH 1024
#define WW 1024
#define PLANES 24           // 8 batch * 3 channels
#define RAD 25
#define TAPS 51

// 50 MB fp16 scratch for the horizontal-pass result (no cudaMalloc allowed)
__device__ __half g_tmp[(size_t)PLANES * HH * WW];

// ---------------- compile-time gaussian weights -> FFMA immediates ----------
struct WTab { float w[TAPS]; };

__host__ __device__ constexpr double cexp_series(double x) {
    double term = 1.0, sum = 1.0;
    for (int i = 1; i < 40; ++i) { term *= x / (double)i; sum += term; }
    return sum;
}

__host__ __device__ constexpr WTab make_wtab() {
    WTab t{};
    double g[TAPS] = {};
    double s = 0.0;
    for (int i = 0; i < TAPS; ++i) {
        double d = (double)(i - RAD);
        g[i] = cexp_series(-d * d / (2.0 * 15.0 * 15.0));
        s += g[i];
    }
    for (int i = 0; i < TAPS; ++i) t.w[i] = (float)(g[i] / s);
    return t;
}

// ---------------- pass 1: horizontal 51-tap conv, no smem / no barriers -----
// One block = one row; 128 threads x 8 outputs. Interior threads read their
// 64-float window straight from global via 16 aligned LDG.128 (lanes overlap
// 94% -> L1 hits); 8 boundary threads take a guarded scalar path.
// Output i at col 8t+i uses loaded element e (col 8t-28+e) with tap d=e-3-i.
__global__ void __launch_bounds__(128) hpass(const float* __restrict__ x) {
    const int row = blockIdx.x;                       // 0 .. PLANES*HH-1
    const float* src = x + (size_t)row * WW;
    __half* dst = g_tmp + (size_t)row * WW;

    const int t = threadIdx.x;
    constexpr WTab WT = make_wtab();

    float acc[8] = {0.f, 0.f, 0.f, 0.f, 0.f, 0.f, 0.f, 0.f};

    if (t >= 4 && t <= 123) {
        // fast path: window cols [8t-28, 8t+35] all within [0,1023]
        const float4* s4 = reinterpret_cast<const float4*>(src + 8 * t - 28);
        #pragma unroll
        for (int k4 = 0; k4 < 16; ++k4) {
            const float4 v4 = __ldg(&s4[k4]);
            const float vv[4] = {v4.x, v4.y, v4.z, v4.w};
            #pragma unroll
            for (int q = 0; q < 4; ++q) {
                const int e = 4 * k4 + q;
                #pragma unroll
                for (int i = 0; i < 8; ++i) {
                    const int d = e - 3 - i;
                    if (d >= 0 && d <= 2 * RAD)
                        acc[i] += WT.w[d] * vv[q];    // FFMA-imm (rt1)
                }
            }
        }
    } else {
        // boundary path: guarded scalar loads (8 threads per row only)
        #pragma unroll
        for (int e = 0; e < 64; ++e) {
            const int col = 8 * t - 28 + e;
            const float v = ((unsigned)col < WW) ? __ldg(src + col) : 0.0f;
            #pragma unroll
            for (int i = 0; i < 8; ++i) {
                const int d = e - 3 - i;
                if (d >= 0 && d <= 2 * RAD)
                    acc[i] += WT.w[d] * v;
            }
        }
    }

    // pack 8 fp32 -> 8 fp16, one STG.128
    union { uint4 u; __half2 h[4]; } o;
    o.h[0] = __floats2half2_rn(acc[0], acc[1]);
    o.h[1] = __floats2half2_rn(acc[2], acc[3]);
    o.h[2] = __floats2half2_rn(acc[4], acc[5]);
    o.h[3] = __floats2half2_rn(acc[6], acc[7]);
    *reinterpret_cast<uint4*>(dst + 8 * t) = o.u;
}

// ---------------- pass 2: streaming vertical conv + blend (no smem) --------
// Thread-per-column, 32 output rows/thread: 82 coalesced fp16 LDGs slide
// down the column into 32 FFMA-imm accumulators. No barriers, no shared mem.
#define VROWS 32

__global__ void __launch_bounds__(256) vpass(const float* __restrict__ x,
                                             const float* __restrict__ amt_p,
                                             float* __restrict__ out) {
    const int tid = threadIdx.x;
    const int plane = blockIdx.z;
    const int c  = blockIdx.x * 256 + tid;           // column 0..1023
    const int y0 = blockIdx.y * VROWS;               // first output row

    const __half* tp = g_tmp + (size_t)plane * HH * WW + c;

    constexpr WTab WT = make_wtab();

    float acc[VROWS];
    #pragma unroll
    for (int i = 0; i < VROWS; ++i) acc[i] = 0.0f;

    // rows y0-25 .. y0+56 (82 loads); out-of-range rows contribute 0
    #pragma unroll
    for (int k = 0; k < VROWS + 2 * RAD; ++k) {
        const int gy = y0 - RAD + k;
        const float v = ((unsigned)gy < HH)
                        ? __half2float(__ldg(tp + (size_t)gy * WW)) : 0.0f;
        #pragma unroll
        for (int i = 0; i < VROWS; ++i) {
            if (k - i >= 0 && k - i <= 2 * RAD)
                acc[i] += WT.w[k - i] * v;           // FFMA-imm (rt1)
        }
    }

    // amount = sigmoid(param)*0.4 ; result = clip(x + blur*1.2*amount*(1-x))
    const float kk = 1.2f * (0.4f / (1.0f + expf(-amt_p[0])));

    const float* xp = x + (size_t)plane * HH * WW + c;
    float* op = out + (size_t)plane * HH * WW + c;

    #pragma unroll
    for (int i = 0; i < VROWS; ++i) {
        const size_t off = (size_t)(y0 + i) * WW;
        const float xv = __ldg(xp + off);
        float r = fmaf(acc[i] * kk, 1.0f - xv, xv);
        op[off] = fminf(fmaxf(r, 0.0f), 1.0f);
    }
}

extern "C" void kernel_launch(void* const* d_in, const int* in_sizes, int n_in,
                              void* d_out, int out_size) {
    const float* x   = (const float*)d_in[0];
    const float* amt = (const float*)d_in[1];
    float* out = (float*)d_out;

    hpass<<<PLANES * HH, 128>>>(x);
    dim3 grid(WW / 256, HH / VROWS, PLANES);         // (4, 32, 24) = 3072 blocks
    vpass<<<grid, 256>>>(x, amt, out);
}